// round 5
// baseline (speedup 1.0000x reference)
#include <cuda_runtime.h>
#include <cstdint>

// Problem constants
#define BATCH 8
#define CH    96
#define NPIX  3136          // 56*56
#define NODES (BATCH*NPIX)  // 25088
#define KNN   9
#define COUT  192

// dist tiling
#define ROWS_B 64           // rows per block
#define CTILE  64           // candidate cols per tile
#define NTILES (NPIX/CTILE) // 49
#define HTILES0 25          // tiles in half 0 (half 1 gets 24)
#define RFS    100          // row-feature smem stride (floats, 16B aligned)
#define CSS    100          // col-feature smem stride
#define DSS    68           // dist tile stride (16B aligned)

typedef unsigned long long u64;

__device__ __forceinline__ void ffma2(u64& d, u64 a, u64 b) {
    asm("fma.rn.f32x2 %0, %1, %2, %3;" : "=l"(d) : "l"(a), "l"(b), "l"(d));
}
__device__ __forceinline__ float2 unpack2(u64 a) {
    float2 r; asm("mov.b64 {%0,%1}, %2;" : "=f"(r.x), "=f"(r.y) : "l"(a)); return r;
}
__device__ __forceinline__ u64 pack2(float lo, float hi) {
    u64 r; asm("mov.b64 %0, {%1,%2};" : "=l"(r) : "f"(lo), "f"(hi)); return r;
}

// ---------------- device scratch (static globals; no allocation) ----------------
__device__ float g_xf[NODES*CH];        // [node, c] node features
__device__ float g_sq[NODES];           // per-node squared norm
__device__ int   g_nn[NODES*KNN];       // global neighbor indices, topk order
__device__ int   g_ki[NODES];           // kept degree per node
__device__ float g_pd[NODES*8*KNN];     // partial topk distances (8 strips)
__device__ int   g_pi[NODES*8*KNN];     // partial topk indices
__device__ float g_W1c[CH*64];          // folded kmap@kfc
__device__ float g_b1c[64];
__device__ float g_W2c[64*KNN];         // folded kmu@kdec
__device__ float g_b2c[KNN];
__device__ float g_Wcat1[192*96];       // [Wa-Wb ; Wb] of ec1
__device__ float g_Wcat2[192*96];       // of ec2
__device__ float g_Wcat3[192*192];      // [io_w@Up1 ; fc_w@Up2]
__device__ float g_bias3[192];
__device__ float g_A1[NODES*192];       // concat feature buffer 1
__device__ float g_A2[NODES*192];       // concat feature buffer 2
__device__ float g_h1[NODES*CH];        // conv1 output

// ---------------- transpose x[B,C,H,W] -> xf[node, c] ----------------
__global__ void transpose_kernel(const float* __restrict__ x) {
    __shared__ float t[32][33];
    int b = blockIdx.z, c0 = blockIdx.y * 32, n0 = blockIdx.x * 32;
    int tx = threadIdx.x, ty = threadIdx.y;
    t[ty][tx] = x[((size_t)b*CH + (c0+ty))*NPIX + (n0+tx)];
    __syncthreads();
    g_xf[((size_t)b*NPIX + (n0+ty))*CH + (c0+tx)] = t[tx][ty];
}

// ---------------- per-node squared norm ----------------
__global__ void sq_kernel() {
    int i = blockIdx.x * blockDim.x + threadIdx.x;
    if (i >= NODES) return;
    const float4* p = (const float4*)(g_xf + (size_t)i*CH);
    float a0=0,a1=0,a2=0,a3=0;
#pragma unroll
    for (int c4 = 0; c4 < CH/4; ++c4) {
        float4 v = p[c4];
        a0 = fmaf(v.x, v.x, a0);
        a1 = fmaf(v.y, v.y, a1);
        a2 = fmaf(v.z, v.z, a2);
        a3 = fmaf(v.w, v.w, a3);
    }
    g_sq[i] = (a0+a1)+(a2+a3);
}

// ---------------- fused weight folding (one launch) ----------------
__global__ __launch_bounds__(256) void mega_prep(
    const float* __restrict__ kmap_w, const float* __restrict__ kmap_b,
    const float* __restrict__ kfc_w,  const float* __restrict__ kfc_b,
    const float* __restrict__ kmu_w,  const float* __restrict__ kmu_b,
    const float* __restrict__ kdec_w, const float* __restrict__ kdec_b,
    const float* __restrict__ ec1_w,  const float* __restrict__ ec2_w,
    const float* __restrict__ io_w,   const float* __restrict__ io_b,
    const float* __restrict__ fc_w,   const float* __restrict__ fc_b,
    const float* __restrict__ up_w,   const float* __restrict__ up_b)
{
    int bid = blockIdx.x;
    if (bid < 24) {
        int idx = bid*256 + threadIdx.x;
        if (idx < CH*64) {
            int c = idx / 64, h = idx % 64;
            float acc = 0.f;
            for (int k = 0; k < 500; ++k) acc = fmaf(kmap_w[c*500+k], kfc_w[k*64+h], acc);
            g_W1c[idx] = acc;
        }
        if (idx < 64) {
            float acc = kfc_b[idx];
            for (int k = 0; k < 500; ++k) acc = fmaf(kmap_b[k], kfc_w[k*64+idx], acc);
            g_b1c[idx] = acc;
        }
    } else if (bid < 27) {
        int idx = (bid-24)*256 + threadIdx.x;
        if (idx < 64*KNN) {
            int h = idx / KNN, j = idx % KNN;
            float acc = 0.f;
            for (int t = 0; t < 32; ++t) acc = fmaf(kmu_w[h*32+t], kdec_w[t*KNN+j], acc);
            g_W2c[idx] = acc;
        }
        if (idx < KNN) {
            float acc = kdec_b[idx];
            for (int t = 0; t < 32; ++t) acc = fmaf(kmu_b[t], kdec_w[t*KNN+idx], acc);
            g_b2c[idx] = acc;
        }
    } else if (bid < 99) {
        int idx = (bid-27)*256 + threadIdx.x;
        if (idx < 192*96) {
            int k = idx / 96;
            g_Wcat1[idx] = (k < 96) ? (ec1_w[idx] - ec1_w[idx + 96*96]) : ec1_w[idx];
        }
    } else if (bid < 171) {
        int idx = (bid-99)*256 + threadIdx.x;
        if (idx < 192*96) {
            int k = idx / 96;
            g_Wcat2[idx] = (k < 96) ? (ec2_w[idx] - ec2_w[idx + 96*96]) : ec2_w[idx];
        }
    } else {
        int idx = (bid-171)*256 + threadIdx.x;
        if (idx < 192*192) {
            int r = idx / 192, j = idx % 192;
            float acc = 0.f;
            if (r < 96) {
                for (int t = 0; t < 192; ++t) acc = fmaf(io_w[r*192+t], up_w[t*192+j], acc);
            } else {
                int c = r - 96;
                for (int t = 0; t < 192; ++t) acc = fmaf(fc_w[c*192+t], up_w[(192+t)*192+j], acc);
            }
            g_Wcat3[idx] = acc;
        }
        if (idx < 192) {
            float acc = up_b[idx];
            for (int t = 0; t < 192; ++t) acc = fmaf(io_b[t], up_w[t*192+idx], acc);
            for (int t = 0; t < 192; ++t) acc = fmaf(fc_b[t], up_w[(192+t)*192+idx], acc);
            g_bias3[idx] = acc;
        }
    }
}

// ---------------- GEMM-tiled distance + exact top-9 (LDS.128 mainloop) ----------------
// Block: 64 rows x one half of the 49 col-tiles. 256 threads, thread tile 4 rows
// x 4 interleaved cols {cx, cx+16, cx+32, cx+48}. k-loop steps 4 floats via
// ulonglong2 (LDS.128): per step 8 LDS.128 feed 32 FFMA2 -> FMA-bound.
// Scan: 64 rows x 4 CONTIGUOUS 16-col strips (ascending cols, strict '<') with
// float4 loads. Per-strip partial top-9 lists -> global; merge_topk8 finishes
// lexicographic in (d, idx) = exact jax.lax.top_k tie semantics.
__global__ __launch_bounds__(256, 2) void dist_topk4() {
    extern __shared__ float smem[];
    float* Rf  = smem;                       // [64][RFS]
    float* Cs  = Rf + ROWS_B*RFS;            // [64][CSS]
    float* Ds  = Cs + CTILE*CSS;             // [64][DSS]
    float* csq = Ds + ROWS_B*DSS;            // [64]

    int tid = threadIdx.x;
    int b    = blockIdx.z;
    int half = blockIdx.y;
    int row0 = blockIdx.x * ROWS_B;
    int grow0 = b * NPIX + row0;
    const float* xb = g_xf + (size_t)b * NPIX * CH;

    // stage row features [64][96] -> Rf (float4 copies)
    for (int idx = tid; idx < ROWS_B*(CH/4); idx += 256) {
        int r = idx / (CH/4), q = idx % (CH/4);
        float4 v = *(const float4*)(g_xf + (size_t)(grow0 + r)*CH + q*4);
        *(float4*)&Rf[r*RFS + q*4] = v;
    }

    // scan identity: row = tid>>2, strip = tid&3 (contiguous 16 cols each)
    int srow = tid >> 2, sstr = tid & 3;
    float rsq = g_sq[grow0 + srow];

    float d[KNN]; int id[KNN];
#pragma unroll
    for (int j = 0; j < KNN; ++j) { d[j] = 3.4e38f; id[j] = 0x7fffffff; }

    int r0 = (tid >> 4) << 2;      // 4 rows r0..r0+3
    int cx = tid & 15;             // 4 interleaved cols cx+16j

    int t0 = half ? HTILES0 : 0;
    int t1 = half ? NTILES  : HTILES0;
    for (int tile = t0; tile < t1; ++tile) {
        int col0 = tile * CTILE;
        // stage candidate features [64][96] -> Cs, plus csq
        for (int idx = tid; idx < CTILE*(CH/4); idx += 256) {
            int c = idx / (CH/4), q = idx % (CH/4);
            float4 v = *(const float4*)(xb + (size_t)(col0 + c)*CH + q*4);
            *(float4*)&Cs[c*CSS + q*4] = v;
        }
        if (tid < CTILE) csq[tid] = g_sq[b*NPIX + col0 + tid];
        __syncthreads();

        // 4x4 outer product over k, LDS.128 per 4 floats (2 f32x2 pairs)
        u64 acc[16];
#pragma unroll
        for (int t = 0; t < 16; ++t) acc[t] = 0ull;
#pragma unroll 2
        for (int k4 = 0; k4 < CH/4; ++k4) {
            ulonglong2 a0 = *(const ulonglong2*)&Rf[(r0+0)*RFS + 4*k4];
            ulonglong2 a1 = *(const ulonglong2*)&Rf[(r0+1)*RFS + 4*k4];
            ulonglong2 a2 = *(const ulonglong2*)&Rf[(r0+2)*RFS + 4*k4];
            ulonglong2 a3 = *(const ulonglong2*)&Rf[(r0+3)*RFS + 4*k4];
            ulonglong2 b0 = *(const ulonglong2*)&Cs[(cx+ 0)*CSS + 4*k4];
            ulonglong2 b1 = *(const ulonglong2*)&Cs[(cx+16)*CSS + 4*k4];
            ulonglong2 b2 = *(const ulonglong2*)&Cs[(cx+32)*CSS + 4*k4];
            ulonglong2 b3 = *(const ulonglong2*)&Cs[(cx+48)*CSS + 4*k4];
            ffma2(acc[ 0], a0.x, b0.x); ffma2(acc[ 1], a0.x, b1.x);
            ffma2(acc[ 2], a0.x, b2.x); ffma2(acc[ 3], a0.x, b3.x);
            ffma2(acc[ 4], a1.x, b0.x); ffma2(acc[ 5], a1.x, b1.x);
            ffma2(acc[ 6], a1.x, b2.x); ffma2(acc[ 7], a1.x, b3.x);
            ffma2(acc[ 8], a2.x, b0.x); ffma2(acc[ 9], a2.x, b1.x);
            ffma2(acc[10], a2.x, b2.x); ffma2(acc[11], a2.x, b3.x);
            ffma2(acc[12], a3.x, b0.x); ffma2(acc[13], a3.x, b1.x);
            ffma2(acc[14], a3.x, b2.x); ffma2(acc[15], a3.x, b3.x);
            ffma2(acc[ 0], a0.y, b0.y); ffma2(acc[ 1], a0.y, b1.y);
            ffma2(acc[ 2], a0.y, b2.y); ffma2(acc[ 3], a0.y, b3.y);
            ffma2(acc[ 4], a1.y, b0.y); ffma2(acc[ 5], a1.y, b1.y);
            ffma2(acc[ 6], a1.y, b2.y); ffma2(acc[ 7], a1.y, b3.y);
            ffma2(acc[ 8], a2.y, b0.y); ffma2(acc[ 9], a2.y, b1.y);
            ffma2(acc[10], a2.y, b2.y); ffma2(acc[11], a2.y, b3.y);
            ffma2(acc[12], a3.y, b0.y); ffma2(acc[13], a3.y, b1.y);
            ffma2(acc[14], a3.y, b2.y); ffma2(acc[15], a3.y, b3.y);
        }
        float q0 = csq[cx+0], q1 = csq[cx+16], q2 = csq[cx+32], q3 = csq[cx+48];
#pragma unroll
        for (int i = 0; i < 4; ++i) {
            float2 s0 = unpack2(acc[i*4+0]);
            float2 s1 = unpack2(acc[i*4+1]);
            float2 s2 = unpack2(acc[i*4+2]);
            float2 s3 = unpack2(acc[i*4+3]);
            float* dr = &Ds[(r0+i)*DSS];
            dr[cx+ 0] = q0 - 2.f*(s0.x + s0.y);
            dr[cx+16] = q1 - 2.f*(s1.x + s1.y);
            dr[cx+32] = q2 - 2.f*(s2.x + s2.y);
            dr[cx+48] = q3 - 2.f*(s3.x + s3.y);
        }
        __syncthreads();

        // strip scan: contiguous 16 cols, ascending, strict '<' insert, float4 loads
        const float* dsrow = &Ds[srow*DSS + sstr*16];
        int gbase = b*NPIX + col0 + sstr*16;
#pragma unroll
        for (int t = 0; t < 4; ++t) {
            float4 dv = *(const float4*)&dsrow[t*4];
            float dcs[4] = {rsq + dv.x, rsq + dv.y, rsq + dv.z, rsq + dv.w};
#pragma unroll
            for (int u = 0; u < 4; ++u) {
                float dc = dcs[u];
                if (dc < d[KNN-1]) {
                    d[KNN-1] = dc; id[KNN-1] = gbase + t*4 + u;
#pragma unroll
                    for (int j = KNN-1; j > 0; --j) {
                        if (d[j] < d[j-1]) {
                            float td = d[j]; d[j] = d[j-1]; d[j-1] = td;
                            int ti = id[j]; id[j] = id[j-1]; id[j-1] = ti;
                        }
                    }
                }
            }
        }
        __syncthreads();   // before next tile overwrites Cs / Ds
    }

    // dump per-strip partials to global
    int str8 = half*4 + sstr;
    size_t base = ((size_t)(grow0 + srow)*8 + str8)*KNN;
#pragma unroll
    for (int j = 0; j < KNN; ++j) { g_pd[base + j] = d[j]; g_pi[base + j] = id[j]; }
}

// ---------------- merge 8 sorted 9-lists per row, (d, idx) lexicographic ----------------
__global__ void merge_topk8() {
    int g = blockIdx.x * 256 + threadIdx.x;
    if (g >= NODES) return;
    const float* pd = g_pd + (size_t)g*8*KNN;
    const int*   pi = g_pi + (size_t)g*8*KNN;
    int p[8] = {0,0,0,0,0,0,0,0};
    int* dst = g_nn + (size_t)g*KNN;
#pragma unroll
    for (int j = 0; j < KNN; ++j) {
        float bd = 3.5e38f; int bi = 0x7fffffff; int sel = 0;
#pragma unroll
        for (int s = 0; s < 8; ++s) {
            if (p[s] < KNN) {
                float dd = pd[s*KNN + p[s]];
                int   ii = pi[s*KNN + p[s]];
                if (dd < bd || (dd == bd && ii < bi)) { bd = dd; bi = ii; sel = s; }
            }
        }
        dst[j] = bi;
        p[sel]++;
    }
}

// ---------------- folded K-predictor MLP + argmax ----------------
__global__ __launch_bounds__(128) void kmlp_kernel() {
    __shared__ float sW1[CH*64];
    __shared__ float sW2[64*KNN];
    __shared__ float sb1[64];
    __shared__ float sb2[KNN];
    for (int t = threadIdx.x; t < CH*64; t += 128) sW1[t] = g_W1c[t];
    for (int t = threadIdx.x; t < 64*KNN; t += 128) sW2[t] = g_W2c[t];
    if (threadIdx.x < 64) sb1[threadIdx.x] = g_b1c[threadIdx.x];
    if (threadIdx.x < KNN) sb2[threadIdx.x] = g_b2c[threadIdx.x];
    __syncthreads();

    int i = blockIdx.x * 128 + threadIdx.x;
    float xr[CH];
#pragma unroll
    for (int c4 = 0; c4 < CH/4; ++c4) {
        float4 v = *(const float4*)(g_xf + (size_t)i*CH + c4*4);
        xr[c4*4+0]=v.x; xr[c4*4+1]=v.y; xr[c4*4+2]=v.z; xr[c4*4+3]=v.w;
    }
    float lg[KNN];
#pragma unroll
    for (int j = 0; j < KNN; ++j) lg[j] = sb2[j];

    for (int h = 0; h < 64; ++h) {
        float a0=0,a1=0,a2=0,a3=0;
#pragma unroll
        for (int c = 0; c < CH; c += 4) {
            a0 = fmaf(xr[c+0], sW1[(c+0)*64+h], a0);
            a1 = fmaf(xr[c+1], sW1[(c+1)*64+h], a1);
            a2 = fmaf(xr[c+2], sW1[(c+2)*64+h], a2);
            a3 = fmaf(xr[c+3], sW1[(c+3)*64+h], a3);
        }
        float hv = fmaxf((a0+a1)+(a2+a3) + sb1[h], 0.f);
#pragma unroll
        for (int j = 0; j < KNN; ++j) lg[j] = fmaf(hv, sW2[h*KNN+j], lg[j]);
    }
    float best = lg[0]; int bi = 0;
#pragma unroll
    for (int j = 1; j < KNN; ++j) if (lg[j] > best) { best = lg[j]; bi = j; }
    g_ki[i] = bi;
}

// ---------------- gather: A = [ki*feat_i | sum_{k<ki} feat_{nn[k]}] ----------------
__global__ void gather_kernel(int mode) {
    const float* feat = mode ? g_h1 : g_xf;
    float*       A    = mode ? g_A2 : g_A1;
    int idx = blockIdx.x * blockDim.x + threadIdx.x;
    if (idx >= NODES*CH) return;
    int i = idx / CH, c = idx % CH;
    int k = g_ki[i];
    const int* nrow = g_nn + (size_t)i*KNN;
    float s = 0.f;
    for (int e = 0; e < k; ++e) s += feat[(size_t)nrow[e]*CH + c];
    A[(size_t)i*192 + c]      = (float)k * feat[(size_t)i*CH + c];
    A[(size_t)i*192 + 96 + c] = s;
}

// ---------------- copy xf into A1[:,0:96] for the final concat ----------------
__global__ void copyxf_kernel() {
    int idx = blockIdx.x * blockDim.x + threadIdx.x;
    if (idx >= NODES*(CH/4)) return;
    int i = idx / (CH/4), c4 = idx % (CH/4);
    ((float4*)(g_A1 + (size_t)i*192))[c4] = ((const float4*)g_xf)[idx];
}

// ---------------- GEMM [25088,192] @ [192, 96-col tile], f32x2-packed ----------------
__global__ __launch_bounds__(256) void gemm_kernel(int mode, const float* __restrict__ bias_in,
                                                   float* __restrict__ dout) {
    const float* A; const float* W; const float* bias; float* C;
    int ldw, ldc, relu, usek, trans;
    if (mode == 0)      { A=g_A1; W=g_Wcat1; bias=bias_in; C=g_h1;    ldw=96;  ldc=96;  relu=1; usek=1; trans=0; }
    else if (mode == 1) { A=g_A2; W=g_Wcat2; bias=bias_in; C=g_A1+96; ldw=96;  ldc=192; relu=0; usek=1; trans=0; }
    else                { A=g_A1; W=g_Wcat3; bias=g_bias3; C=dout;    ldw=192; ldc=192; relu=1; usek=0; trans=1; }

    __shared__ float As[16][128];
    __shared__ float Bs[16][96];
    int tid = threadIdx.x;
    int tx = tid % 16, ty = tid / 16;
    int row0 = blockIdx.x * 128;
    int col0 = blockIdx.y * 96;

    u64 acc2[4][6];
#pragma unroll
    for (int p = 0; p < 4; ++p)
#pragma unroll
        for (int j = 0; j < 6; ++j) acc2[p][j] = 0ull;

    for (int kk = 0; kk < 192; kk += 16) {
#pragma unroll
        for (int l = 0; l < 2; ++l) {
            int idx = tid + l*256;
            int r = idx >> 2, k4 = idx & 3;
            float4 v = *(const float4*)(A + (size_t)(row0 + r)*192 + kk + k4*4);
            As[k4*4+0][r] = v.x; As[k4*4+1][r] = v.y; As[k4*4+2][r] = v.z; As[k4*4+3][r] = v.w;
        }
#pragma unroll
        for (int l = 0; l < 2; ++l) {
            int idx = tid + l*256;
            if (idx < 384) {
                int k = idx / 24, c4 = idx % 24;
                float4 v = *(const float4*)(W + (size_t)(kk+k)*ldw + col0 + c4*4);
                *(float4*)&Bs[k][c4*4] = v;
            }
        }
        __syncthreads();
#pragma unroll
        for (int k = 0; k < 16; ++k) {
            ulonglong2 a01 = *(const ulonglong2*)&As[k][ty*8];
            ulonglong2 a23 = *(const ulonglong2*)&As[k][ty*8+4];
            u64 ap[4] = {a01.x, a01.y, a23.x, a23.y};
            float2 bv0 = *(const float2*)&Bs[k][tx*6];
            float2 bv1 = *(const float2*)&Bs[k][tx*6+2];
            float2 bv2 = *(const float2*)&Bs[k][tx*6+4];
            u64 bp[6];
            bp[0] = pack2(bv0.x, bv0.x); bp[1] = pack2(bv0.y, bv0.y);
            bp[2] = pack2(bv1.x, bv1.x); bp[3] = pack2(bv1.y, bv1.y);
            bp[4] = pack2(bv2.x, bv2.x); bp[5] = pack2(bv2.y, bv2.y);
#pragma unroll
            for (int p = 0; p < 4; ++p)
#pragma unroll
                for (int j = 0; j < 6; ++j) ffma2(acc2[p][j], ap[p], bp[j]);
        }
        __syncthreads();
    }

#pragma unroll
    for (int p = 0; p < 4; ++p) {
        int rlo = row0 + ty*8 + 2*p;
        float klo = usek ? (float)g_ki[rlo]   : 1.f;
        float khi = usek ? (float)g_ki[rlo+1] : 1.f;
#pragma unroll
        for (int j = 0; j < 6; ++j) {
            int col = col0 + tx*6 + j;
            float2 v2 = unpack2(acc2[p][j]);
            float vlo = v2.x + bias[col] * klo;
            float vhi = v2.y + bias[col] * khi;
            if (relu) { vlo = fmaxf(vlo, 0.f); vhi = fmaxf(vhi, 0.f); }
            if (trans) {
                int blo = rlo / NPIX, nlo = rlo % NPIX;
                int bhi = (rlo+1) / NPIX, nhi = (rlo+1) % NPIX;
                C[((size_t)(blo*192 + col))*NPIX + nlo] = vlo;
                C[((size_t)(bhi*192 + col))*NPIX + nhi] = vhi;
            } else {
                C[(size_t)rlo*ldc + col]     = vlo;
                C[(size_t)(rlo+1)*ldc + col] = vhi;
            }
        }
    }
}

// ---------------- launch ----------------
extern "C" void kernel_launch(void* const* d_in, const int* in_sizes, int n_in,
                              void* d_out, int out_size) {
    const float* x      = (const float*)d_in[0];
    const float* kmap_w = (const float*)d_in[1];
    const float* kmap_b = (const float*)d_in[2];
    const float* kfc_w  = (const float*)d_in[3];
    const float* kfc_b  = (const float*)d_in[4];
    const float* kmu_w  = (const float*)d_in[5];
    const float* kmu_b  = (const float*)d_in[6];
    const float* kdec_w = (const float*)d_in[7];
    const float* kdec_b = (const float*)d_in[8];
    const float* ec1_w  = (const float*)d_in[9];
    const float* ec1_b  = (const float*)d_in[10];
    const float* ec2_w  = (const float*)d_in[11];
    const float* ec2_b  = (const float*)d_in[12];
    const float* fc_w   = (const float*)d_in[13];
    const float* fc_b   = (const float*)d_in[14];
    const float* io_w   = (const float*)d_in[15];
    const float* io_b   = (const float*)d_in[16];
    const float* up_w   = (const float*)d_in[17];
    const float* up_b   = (const float*)d_in[18];
    float* out = (float*)d_out;

    const int dist_smem = (ROWS_B*RFS + CTILE*CSS + ROWS_B*DSS + CTILE) * 4;
    cudaFuncSetAttribute(dist_topk4, cudaFuncAttributeMaxDynamicSharedMemorySize, dist_smem);

    transpose_kernel<<<dim3(NPIX/32, CH/32, BATCH), dim3(32,32)>>>(x);
    sq_kernel<<<(NODES+255)/256, 256>>>();
    mega_prep<<<315, 256>>>(kmap_w, kmap_b, kfc_w, kfc_b, kmu_w, kmu_b,
                            kdec_w, kdec_b, ec1_w, ec2_w,
                            io_w, io_b, fc_w, fc_b, up_w, up_b);

    dist_topk4<<<dim3(NPIX/ROWS_B, 2, BATCH), 256, dist_smem>>>();
    merge_topk8<<<(NODES+255)/256, 256>>>();
    kmlp_kernel<<<NODES/128, 128>>>();

    gather_kernel<<<(NODES*CH+255)/256, 256>>>(0);
    gemm_kernel<<<dim3(NODES/128, 1), 256>>>(0, ec1_b, nullptr);
    gather_kernel<<<(NODES*CH+255)/256, 256>>>(1);
    copyxf_kernel<<<(NODES*(CH/4)+255)/256, 256>>>();
    gemm_kernel<<<dim3(NODES/128, 1), 256>>>(1, ec2_b, nullptr);
    gemm_kernel<<<dim3(NODES/128, 2), 256>>>(2, nullptr, out);
    (void)in_sizes; (void)n_in; (void)out_size;
}

// round 6
// speedup vs baseline: 1.7420x; 1.7420x over previous
#include <cuda_runtime.h>
#include <cstdint>

// Problem constants
#define BATCH 8
#define CH    96
#define NPIX  3136          // 56*56
#define NODES (BATCH*NPIX)  // 25088
#define KNN   9
#define COUT  192

// dist tiling
#define ROWS_B 64           // rows per block
#define CTILE  64           // candidate cols per tile
#define NTILES (NPIX/CTILE) // 49
#define RFS    98           // row-feature smem stride (floats); bank stride 2 -> conflict-free
#define CSS    98           // col-feature smem stride
#define DSS    68           // dist tile stride (multiple of 4 for float4 scan loads)

typedef unsigned long long u64;

__device__ __forceinline__ void ffma2(u64& d, u64 a, u64 b) {
    asm("fma.rn.f32x2 %0, %1, %2, %3;" : "=l"(d) : "l"(a), "l"(b), "l"(d));
}
__device__ __forceinline__ float2 unpack2(u64 a) {
    float2 r; asm("mov.b64 {%0,%1}, %2;" : "=f"(r.x), "=f"(r.y) : "l"(a)); return r;
}
__device__ __forceinline__ u64 pack2(float lo, float hi) {
    u64 r; asm("mov.b64 %0, {%1,%2};" : "=l"(r) : "f"(lo), "f"(hi)); return r;
}

// ---------------- device scratch (static globals; no allocation) ----------------
__device__ float g_xf[NODES*CH];        // [node, c] node features
__device__ float g_sq[NODES];           // per-node squared norm
__device__ int   g_nn[NODES*KNN];       // global neighbor indices, topk order
__device__ int   g_ki[NODES];           // kept degree per node
__device__ float g_W1c[CH*64];          // folded kmap@kfc
__device__ float g_b1c[64];
__device__ float g_W2c[64*KNN];         // folded kmu@kdec
__device__ float g_b2c[KNN];
__device__ float g_Wcat1[192*96];       // [Wa-Wb ; Wb] of ec1
__device__ float g_Wcat2[192*96];       // of ec2
__device__ float g_Wcat3[192*192];      // [io_w@Up1 ; fc_w@Up2]
__device__ float g_bias3[192];
__device__ float g_A1[NODES*192];       // concat feature buffer 1
__device__ float g_A2[NODES*192];       // concat feature buffer 2
__device__ float g_h1[NODES*CH];        // conv1 output

// ---------------- transpose x[B,C,H,W] -> xf[node, c] ----------------
__global__ void transpose_kernel(const float* __restrict__ x) {
    __shared__ float t[32][33];
    int b = blockIdx.z, c0 = blockIdx.y * 32, n0 = blockIdx.x * 32;
    int tx = threadIdx.x, ty = threadIdx.y;
    t[ty][tx] = x[((size_t)b*CH + (c0+ty))*NPIX + (n0+tx)];
    __syncthreads();
    g_xf[((size_t)b*NPIX + (n0+ty))*CH + (c0+tx)] = t[tx][ty];
}

// ---------------- per-node squared norm ----------------
__global__ void sq_kernel() {
    int i = blockIdx.x * blockDim.x + threadIdx.x;
    if (i >= NODES) return;
    const float4* p = (const float4*)(g_xf + (size_t)i*CH);
    float a0=0,a1=0,a2=0,a3=0;
#pragma unroll
    for (int c4 = 0; c4 < CH/4; ++c4) {
        float4 v = p[c4];
        a0 = fmaf(v.x, v.x, a0);
        a1 = fmaf(v.y, v.y, a1);
        a2 = fmaf(v.z, v.z, a2);
        a3 = fmaf(v.w, v.w, a3);
    }
    g_sq[i] = (a0+a1)+(a2+a3);
}

// ---------------- fused weight folding (one launch) ----------------
__global__ __launch_bounds__(256) void mega_prep(
    const float* __restrict__ kmap_w, const float* __restrict__ kmap_b,
    const float* __restrict__ kfc_w,  const float* __restrict__ kfc_b,
    const float* __restrict__ kmu_w,  const float* __restrict__ kmu_b,
    const float* __restrict__ kdec_w, const float* __restrict__ kdec_b,
    const float* __restrict__ ec1_w,  const float* __restrict__ ec2_w,
    const float* __restrict__ io_w,   const float* __restrict__ io_b,
    const float* __restrict__ fc_w,   const float* __restrict__ fc_b,
    const float* __restrict__ up_w,   const float* __restrict__ up_b)
{
    int bid = blockIdx.x;
    if (bid < 24) {
        int idx = bid*256 + threadIdx.x;
        if (idx < CH*64) {
            int c = idx / 64, h = idx % 64;
            float acc = 0.f;
            for (int k = 0; k < 500; ++k) acc = fmaf(kmap_w[c*500+k], kfc_w[k*64+h], acc);
            g_W1c[idx] = acc;
        }
        if (idx < 64) {
            float acc = kfc_b[idx];
            for (int k = 0; k < 500; ++k) acc = fmaf(kmap_b[k], kfc_w[k*64+idx], acc);
            g_b1c[idx] = acc;
        }
    } else if (bid < 27) {
        int idx = (bid-24)*256 + threadIdx.x;
        if (idx < 64*KNN) {
            int h = idx / KNN, j = idx % KNN;
            float acc = 0.f;
            for (int t = 0; t < 32; ++t) acc = fmaf(kmu_w[h*32+t], kdec_w[t*KNN+j], acc);
            g_W2c[idx] = acc;
        }
        if (idx < KNN) {
            float acc = kdec_b[idx];
            for (int t = 0; t < 32; ++t) acc = fmaf(kmu_b[t], kdec_w[t*KNN+idx], acc);
            g_b2c[idx] = acc;
        }
    } else if (bid < 99) {
        int idx = (bid-27)*256 + threadIdx.x;
        if (idx < 192*96) {
            int k = idx / 96;
            g_Wcat1[idx] = (k < 96) ? (ec1_w[idx] - ec1_w[idx + 96*96]) : ec1_w[idx];
        }
    } else if (bid < 171) {
        int idx = (bid-99)*256 + threadIdx.x;
        if (idx < 192*96) {
            int k = idx / 96;
            g_Wcat2[idx] = (k < 96) ? (ec2_w[idx] - ec2_w[idx + 96*96]) : ec2_w[idx];
        }
    } else {
        int idx = (bid-171)*256 + threadIdx.x;
        if (idx < 192*192) {
            int r = idx / 192, j = idx % 192;
            float acc = 0.f;
            if (r < 96) {
                for (int t = 0; t < 192; ++t) acc = fmaf(io_w[r*192+t], up_w[t*192+j], acc);
            } else {
                int c = r - 96;
                for (int t = 0; t < 192; ++t) acc = fmaf(fc_w[c*192+t], up_w[(192+t)*192+j], acc);
            }
            g_Wcat3[idx] = acc;
        }
        if (idx < 192) {
            float acc = up_b[idx];
            for (int t = 0; t < 192; ++t) acc = fmaf(io_b[t], up_w[t*192+idx], acc);
            for (int t = 0; t < 192; ++t) acc = fmaf(fc_b[t], up_w[(192+t)*192+idx], acc);
            g_bias3[idx] = acc;
        }
    }
}

// ---------------- GEMM-tiled distance + exact top-9 (4x8 thread tile) ----------------
// 128 threads/block, 3 blocks/SM, single wave (392 blocks). Block: 64 rows x all
// 49 tiles of 64 cols. Thread tile 4 rows x 8 interleaved cols {ct+8j}: per k-pair
// 12 one-phase LDS.64 feed 32 FFMA2 -> FMA-bound. Scan: 2 strips/row of 32
// contiguous cols, ascending, strict '<'; in-block lexicographic 2-way merge
// reproduces exact jax.lax.top_k tie semantics.
__global__ __launch_bounds__(128, 3) void dist_topk5() {
    extern __shared__ float smem[];
    float* Rf  = smem;                       // [64][RFS]
    float* Cs  = Rf + ROWS_B*RFS;            // [64][CSS]
    float* Ds  = Cs + CTILE*CSS;             // [64][DSS]
    float* csq = Ds + ROWS_B*DSS;            // [64]

    int tid = threadIdx.x;
    int b    = blockIdx.y;
    int row0 = blockIdx.x * ROWS_B;
    int grow0 = b * NPIX + row0;
    const float* xb = g_xf + (size_t)b * NPIX * CH;

    // stage row features [64][96] -> Rf (float2, stride-98 safe)
    for (int idx = tid; idx < ROWS_B*(CH/2); idx += 128) {
        int r = idx / (CH/2), k2 = idx % (CH/2);
        *(float2*)&Rf[r*RFS + k2*2] =
            *(const float2*)(g_xf + (size_t)(grow0 + r)*CH + k2*2);
    }

    // mainloop identity: 4 rows x 8 interleaved cols
    int r0 = (tid >> 3) << 2;      // rows r0..r0+3
    int ct = tid & 7;              // cols ct + 8j

    // scan identity: row = tid>>1, strip = tid&1 (contiguous 32 cols)
    int srow = tid >> 1, sstr = tid & 1;
    float rsq = g_sq[grow0 + srow];

    float d[KNN]; int id[KNN];
#pragma unroll
    for (int j = 0; j < KNN; ++j) { d[j] = 3.4e38f; id[j] = 0x7fffffff; }

    for (int tile = 0; tile < NTILES; ++tile) {
        int col0 = tile * CTILE;
        // stage candidate features [64][96] -> Cs, plus csq
        for (int idx = tid; idx < CTILE*(CH/2); idx += 128) {
            int c = idx / (CH/2), k2 = idx % (CH/2);
            *(float2*)&Cs[c*CSS + k2*2] =
                *(const float2*)(xb + (size_t)(col0 + c)*CH + k2*2);
        }
        if (tid < CTILE) csq[tid] = g_sq[b*NPIX + col0 + tid];
        __syncthreads();

        // 4x8 outer product over k (f32x2 pairs)
        u64 acc[4][8];
#pragma unroll
        for (int i = 0; i < 4; ++i)
#pragma unroll
            for (int j = 0; j < 8; ++j) acc[i][j] = 0ull;
#pragma unroll 4
        for (int k2 = 0; k2 < CH/2; ++k2) {
            u64 b0 = *(const u64*)&Cs[(ct+ 0)*CSS + 2*k2];
            u64 b1 = *(const u64*)&Cs[(ct+ 8)*CSS + 2*k2];
            u64 b2 = *(const u64*)&Cs[(ct+16)*CSS + 2*k2];
            u64 b3 = *(const u64*)&Cs[(ct+24)*CSS + 2*k2];
            u64 b4 = *(const u64*)&Cs[(ct+32)*CSS + 2*k2];
            u64 b5 = *(const u64*)&Cs[(ct+40)*CSS + 2*k2];
            u64 b6 = *(const u64*)&Cs[(ct+48)*CSS + 2*k2];
            u64 b7 = *(const u64*)&Cs[(ct+56)*CSS + 2*k2];
#pragma unroll
            for (int i = 0; i < 4; ++i) {
                u64 av = *(const u64*)&Rf[(r0+i)*RFS + 2*k2];
                ffma2(acc[i][0], av, b0); ffma2(acc[i][1], av, b1);
                ffma2(acc[i][2], av, b2); ffma2(acc[i][3], av, b3);
                ffma2(acc[i][4], av, b4); ffma2(acc[i][5], av, b5);
                ffma2(acc[i][6], av, b6); ffma2(acc[i][7], av, b7);
            }
        }
#pragma unroll
        for (int i = 0; i < 4; ++i) {
            float* dr = &Ds[(r0+i)*DSS];
#pragma unroll
            for (int j = 0; j < 8; ++j) {
                float2 s = unpack2(acc[i][j]);
                dr[ct + 8*j] = csq[ct + 8*j] - 2.f*(s.x + s.y);
            }
        }
        __syncthreads();

        // strip scan: 32 contiguous cols, ascending, strict '<' insert
        const float* dsrow = &Ds[srow*DSS + sstr*32];
        int gbase = b*NPIX + col0 + sstr*32;
#pragma unroll
        for (int t = 0; t < 8; ++t) {
            float4 dv = *(const float4*)&dsrow[t*4];
            float dcs[4] = {rsq + dv.x, rsq + dv.y, rsq + dv.z, rsq + dv.w};
#pragma unroll
            for (int u = 0; u < 4; ++u) {
                float dc = dcs[u];
                if (dc < d[KNN-1]) {
                    d[KNN-1] = dc; id[KNN-1] = gbase + t*4 + u;
#pragma unroll
                    for (int j = KNN-1; j > 0; --j) {
                        if (d[j] < d[j-1]) {
                            float td = d[j]; d[j] = d[j-1]; d[j-1] = td;
                            int ti = id[j]; id[j] = id[j-1]; id[j-1] = ti;
                        }
                    }
                }
            }
        }
        __syncthreads();   // scans done before next tile restages Cs / rewrites Ds
    }

    // in-block merge of the 2 strips per row (lexicographic in (d, idx))
    float* pd = Cs;              // reuse smem
    int*   pi = (int*)Rf;
#pragma unroll
    for (int j = 0; j < KNN; ++j) { pd[tid*KNN + j] = d[j]; pi[tid*KNN + j] = id[j]; }
    __syncthreads();
    if (sstr == 0) {
        const float* dA = &pd[tid*KNN];      const int* iA = &pi[tid*KNN];
        const float* dB = &pd[(tid+1)*KNN];  const int* iB = &pi[(tid+1)*KNN];
        int p = 0, q = 0;
        int* dst = g_nn + (size_t)(grow0 + srow)*KNN;
#pragma unroll
        for (int j = 0; j < KNN; ++j) {
            float da = dA[p], db = dB[q];
            bool takeA = (da < db) || (da == db && iA[p] < iB[q]);
            dst[j] = takeA ? iA[p++] : iB[q++];
        }
    }
}

// ---------------- folded K-predictor MLP + argmax ----------------
__global__ __launch_bounds__(128) void kmlp_kernel() {
    __shared__ float sW1[CH*64];
    __shared__ float sW2[64*KNN];
    __shared__ float sb1[64];
    __shared__ float sb2[KNN];
    for (int t = threadIdx.x; t < CH*64; t += 128) sW1[t] = g_W1c[t];
    for (int t = threadIdx.x; t < 64*KNN; t += 128) sW2[t] = g_W2c[t];
    if (threadIdx.x < 64) sb1[threadIdx.x] = g_b1c[threadIdx.x];
    if (threadIdx.x < KNN) sb2[threadIdx.x] = g_b2c[threadIdx.x];
    __syncthreads();

    int i = blockIdx.x * 128 + threadIdx.x;
    float xr[CH];
#pragma unroll
    for (int c4 = 0; c4 < CH/4; ++c4) {
        float4 v = *(const float4*)(g_xf + (size_t)i*CH + c4*4);
        xr[c4*4+0]=v.x; xr[c4*4+1]=v.y; xr[c4*4+2]=v.z; xr[c4*4+3]=v.w;
    }
    float lg[KNN];
#pragma unroll
    for (int j = 0; j < KNN; ++j) lg[j] = sb2[j];

    for (int h = 0; h < 64; ++h) {
        float a0=0,a1=0,a2=0,a3=0;
#pragma unroll
        for (int c = 0; c < CH; c += 4) {
            a0 = fmaf(xr[c+0], sW1[(c+0)*64+h], a0);
            a1 = fmaf(xr[c+1], sW1[(c+1)*64+h], a1);
            a2 = fmaf(xr[c+2], sW1[(c+2)*64+h], a2);
            a3 = fmaf(xr[c+3], sW1[(c+3)*64+h], a3);
        }
        float hv = fmaxf((a0+a1)+(a2+a3) + sb1[h], 0.f);
#pragma unroll
        for (int j = 0; j < KNN; ++j) lg[j] = fmaf(hv, sW2[h*KNN+j], lg[j]);
    }
    float best = lg[0]; int bi = 0;
#pragma unroll
    for (int j = 1; j < KNN; ++j) if (lg[j] > best) { best = lg[j]; bi = j; }
    g_ki[i] = bi;
}

// ---------------- gather: A = [ki*feat_i | sum_{k<ki} feat_{nn[k]}] ----------------
__global__ void gather_kernel(int mode) {
    const float* feat = mode ? g_h1 : g_xf;
    float*       A    = mode ? g_A2 : g_A1;
    int idx = blockIdx.x * blockDim.x + threadIdx.x;
    if (idx >= NODES*CH) return;
    int i = idx / CH, c = idx % CH;
    int k = g_ki[i];
    const int* nrow = g_nn + (size_t)i*KNN;
    float s = 0.f;
    for (int e = 0; e < k; ++e) s += feat[(size_t)nrow[e]*CH + c];
    A[(size_t)i*192 + c]      = (float)k * feat[(size_t)i*CH + c];
    A[(size_t)i*192 + 96 + c] = s;
}

// ---------------- copy xf into A1[:,0:96] for the final concat ----------------
__global__ void copyxf_kernel() {
    int idx = blockIdx.x * blockDim.x + threadIdx.x;
    if (idx >= NODES*(CH/4)) return;
    int i = idx / (CH/4), c4 = idx % (CH/4);
    ((float4*)(g_A1 + (size_t)i*192))[c4] = ((const float4*)g_xf)[idx];
}

// ---------------- GEMM [25088,192] @ [192, 96-col tile], f32x2-packed ----------------
__global__ __launch_bounds__(256) void gemm_kernel(int mode, const float* __restrict__ bias_in,
                                                   float* __restrict__ dout) {
    const float* A; const float* W; const float* bias; float* C;
    int ldw, ldc, relu, usek, trans;
    if (mode == 0)      { A=g_A1; W=g_Wcat1; bias=bias_in; C=g_h1;    ldw=96;  ldc=96;  relu=1; usek=1; trans=0; }
    else if (mode == 1) { A=g_A2; W=g_Wcat2; bias=bias_in; C=g_A1+96; ldw=96;  ldc=192; relu=0; usek=1; trans=0; }
    else                { A=g_A1; W=g_Wcat3; bias=g_bias3; C=dout;    ldw=192; ldc=192; relu=1; usek=0; trans=1; }

    __shared__ float As[16][128];
    __shared__ float Bs[16][96];
    int tid = threadIdx.x;
    int tx = tid % 16, ty = tid / 16;
    int row0 = blockIdx.x * 128;
    int col0 = blockIdx.y * 96;

    u64 acc2[4][6];
#pragma unroll
    for (int p = 0; p < 4; ++p)
#pragma unroll
        for (int j = 0; j < 6; ++j) acc2[p][j] = 0ull;

    for (int kk = 0; kk < 192; kk += 16) {
#pragma unroll
        for (int l = 0; l < 2; ++l) {
            int idx = tid + l*256;
            int r = idx >> 2, k4 = idx & 3;
            float4 v = *(const float4*)(A + (size_t)(row0 + r)*192 + kk + k4*4);
            As[k4*4+0][r] = v.x; As[k4*4+1][r] = v.y; As[k4*4+2][r] = v.z; As[k4*4+3][r] = v.w;
        }
#pragma unroll
        for (int l = 0; l < 2; ++l) {
            int idx = tid + l*256;
            if (idx < 384) {
                int k = idx / 24, c4 = idx % 24;
                float4 v = *(const float4*)(W + (size_t)(kk+k)*ldw + col0 + c4*4);
                *(float4*)&Bs[k][c4*4] = v;
            }
        }
        __syncthreads();
#pragma unroll
        for (int k = 0; k < 16; ++k) {
            ulonglong2 a01 = *(const ulonglong2*)&As[k][ty*8];
            ulonglong2 a23 = *(const ulonglong2*)&As[k][ty*8+4];
            u64 ap[4] = {a01.x, a01.y, a23.x, a23.y};
            float2 bv0 = *(const float2*)&Bs[k][tx*6];
            float2 bv1 = *(const float2*)&Bs[k][tx*6+2];
            float2 bv2 = *(const float2*)&Bs[k][tx*6+4];
            u64 bp[6];
            bp[0] = pack2(bv0.x, bv0.x); bp[1] = pack2(bv0.y, bv0.y);
            bp[2] = pack2(bv1.x, bv1.x); bp[3] = pack2(bv1.y, bv1.y);
            bp[4] = pack2(bv2.x, bv2.x); bp[5] = pack2(bv2.y, bv2.y);
#pragma unroll
            for (int p = 0; p < 4; ++p)
#pragma unroll
                for (int j = 0; j < 6; ++j) ffma2(acc2[p][j], ap[p], bp[j]);
        }
        __syncthreads();
    }

#pragma unroll
    for (int p = 0; p < 4; ++p) {
        int rlo = row0 + ty*8 + 2*p;
        float klo = usek ? (float)g_ki[rlo]   : 1.f;
        float khi = usek ? (float)g_ki[rlo+1] : 1.f;
#pragma unroll
        for (int j = 0; j < 6; ++j) {
            int col = col0 + tx*6 + j;
            float2 v2 = unpack2(acc2[p][j]);
            float vlo = v2.x + bias[col] * klo;
            float vhi = v2.y + bias[col] * khi;
            if (relu) { vlo = fmaxf(vlo, 0.f); vhi = fmaxf(vhi, 0.f); }
            if (trans) {
                int blo = rlo / NPIX, nlo = rlo % NPIX;
                int bhi = (rlo+1) / NPIX, nhi = (rlo+1) % NPIX;
                C[((size_t)(blo*192 + col))*NPIX + nlo] = vlo;
                C[((size_t)(bhi*192 + col))*NPIX + nhi] = vhi;
            } else {
                C[(size_t)rlo*ldc + col]     = vlo;
                C[(size_t)(rlo+1)*ldc + col] = vhi;
            }
        }
    }
}

// ---------------- launch ----------------
extern "C" void kernel_launch(void* const* d_in, const int* in_sizes, int n_in,
                              void* d_out, int out_size) {
    const float* x      = (const float*)d_in[0];
    const float* kmap_w = (const float*)d_in[1];
    const float* kmap_b = (const float*)d_in[2];
    const float* kfc_w  = (const float*)d_in[3];
    const float* kfc_b  = (const float*)d_in[4];
    const float* kmu_w  = (const float*)d_in[5];
    const float* kmu_b  = (const float*)d_in[6];
    const float* kdec_w = (const float*)d_in[7];
    const float* kdec_b = (const float*)d_in[8];
    const float* ec1_w  = (const float*)d_in[9];
    const float* ec1_b  = (const float*)d_in[10];
    const float* ec2_w  = (const float*)d_in[11];
    const float* ec2_b  = (const float*)d_in[12];
    const float* fc_w   = (const float*)d_in[13];
    const float* fc_b   = (const float*)d_in[14];
    const float* io_w   = (const float*)d_in[15];
    const float* io_b   = (const float*)d_in[16];
    const float* up_w   = (const float*)d_in[17];
    const float* up_b   = (const float*)d_in[18];
    float* out = (float*)d_out;

    const int dist_smem = (ROWS_B*RFS + CTILE*CSS + ROWS_B*DSS + CTILE) * 4;
    cudaFuncSetAttribute(dist_topk5, cudaFuncAttributeMaxDynamicSharedMemorySize, dist_smem);

    transpose_kernel<<<dim3(NPIX/32, CH/32, BATCH), dim3(32,32)>>>(x);
    sq_kernel<<<(NODES+255)/256, 256>>>();
    mega_prep<<<315, 256>>>(kmap_w, kmap_b, kfc_w, kfc_b, kmu_w, kmu_b,
                            kdec_w, kdec_b, ec1_w, ec2_w,
                            io_w, io_b, fc_w, fc_b, up_w, up_b);

    dist_topk5<<<dim3(NPIX/ROWS_B, BATCH), 128, dist_smem>>>();
    kmlp_kernel<<<NODES/128, 128>>>();

    gather_kernel<<<(NODES*CH+255)/256, 256>>>(0);
    gemm_kernel<<<dim3(NODES/128, 1), 256>>>(0, ec1_b, nullptr);
    gather_kernel<<<(NODES*CH+255)/256, 256>>>(1);
    copyxf_kernel<<<(NODES*(CH/4)+255)/256, 256>>>();
    gemm_kernel<<<dim3(NODES/128, 1), 256>>>(1, ec2_b, nullptr);
    gemm_kernel<<<dim3(NODES/128, 2), 256>>>(2, nullptr, out);
    (void)in_sizes; (void)n_in; (void)out_size;
}